// round 7
// baseline (speedup 1.0000x reference)
#include <cuda_runtime.h>
#include <cuda_fp16.h>
#include <cstdint>

// Problem constants (fixed by the reference)
#define NN 50000
#define NE 600000
#define NG 64
#define D_IN 128
#define D_HID 128
#define D_OUT 64

// ---------------- device scratch (no allocs allowed) ----------------
// Invariant: g_cnt, g_gsum, g_gcnt, g_done are ZERO at entry of every
// kernel_launch call (BSS-zero initially; each run re-zeroes them before
// finishing). Keeps the captured graph deterministic across replays.
__device__ __align__(16) int    g_cnt[NN];        // in-degree (edges only)
__device__ __align__(16) float  g_dinv[NN];
__device__ __align__(16) int    g_rowptr[NN + 1];
__device__ __align__(16) int    g_fillptr[NN];
__device__ __align__(16) int    g_col[NE];
__device__ __align__(16) __half g_hs1[NN * D_HID];   // (x@W1)*dinv[row], fp16
__device__ __align__(16) __half g_out1[NN * D_HID];  // relu(layer1 agg), fp16
__device__ __align__(16) __half g_hs2[NN * D_OUT];   // (out1@W2)*dinv[row], fp16
__device__ __align__(16) float  g_gsum[NG * D_OUT];
__device__ __align__(16) int    g_gcnt[NG];
__device__ int g_done;

// ---------------- degree + graph-size histogram (fused) ----------------
__global__ void k_deg(const int* __restrict__ ei, const int* __restrict__ batch,
                      int e, int n) {
    __shared__ int hist[NG];
    int t = threadIdx.x;
    if (t < NG) hist[t] = 0;
    __syncthreads();
    int i = blockIdx.x * blockDim.x + t;
    if (i < e) atomicAdd(&g_cnt[ei[e + i]], 1);
    if (i < n) atomicAdd(&hist[batch[i]], 1);
    __syncthreads();
    if (t < NG && hist[t]) atomicAdd(&g_gcnt[t], hist[t]);
}

// ---------------- fused CSR scan (single block, 1024 threads) ----------
// exclusive-scan g_cnt -> g_rowptr/g_fillptr, dinv = rsqrt(cnt+1),
// rowptr[n] = e. Replaces the old 3-kernel scan chain.
__global__ __launch_bounds__(1024) void k_scan(int n, int e) {
    __shared__ int s[1024];
    const int T = 1024;
    int t = threadIdx.x;
    int per = (n + T - 1) / T;                    // 49
    int start = t * per;
    int end = min(start + per, n);

    int sum = 0;
    for (int i = start; i < end; i++) sum += g_cnt[i];

    s[t] = sum;
    __syncthreads();
    #pragma unroll
    for (int off = 1; off < T; off <<= 1) {
        int add = (t >= off) ? s[t - off] : 0;
        __syncthreads();
        s[t] += add;
        __syncthreads();
    }
    int run = s[t] - sum;                         // exclusive prefix

    for (int i = start; i < end; i++) {
        int c = g_cnt[i];
        g_rowptr[i]  = run;
        g_fillptr[i] = run;
        g_dinv[i]    = rsqrtf((float)(c + 1));    // self-loop folded
        run += c;
    }
    if (t == 0) g_rowptr[n] = e;
}

// fill CSR cols; re-zero g_cnt for the next replay
__global__ void k_fill(const int* __restrict__ ei, int e, int n) {
    int i = blockIdx.x * blockDim.x + threadIdx.x;
    if (i < e) {
        int s = ei[i];
        int d = ei[e + i];
        int pos = atomicAdd(&g_fillptr[d], 1);
        g_col[pos] = s;
    }
    if (i < n) g_cnt[i] = 0;
}

// ---------------- tensor-core GEMM ----------------
// out[r,:] = half( (X[r,:128] @ W[:128,:N]) * dinv[r] )
// LAYER=1: X = fp32 arg -> g_hs1.  LAYER=2: X = g_out1 (fp16) -> g_hs2.
__device__ __forceinline__ uint32_t smem_u32(const void* p) {
    return (uint32_t)__cvta_generic_to_shared(p);
}
__device__ __forceinline__ void ldsm_x4(uint32_t& a0, uint32_t& a1,
                                        uint32_t& a2, uint32_t& a3, uint32_t addr) {
    asm volatile("ldmatrix.sync.aligned.m8n8.x4.shared.b16 {%0,%1,%2,%3},[%4];"
                 : "=r"(a0), "=r"(a1), "=r"(a2), "=r"(a3) : "r"(addr));
}
__device__ __forceinline__ void ldsm_x2t(uint32_t& b0, uint32_t& b1, uint32_t addr) {
    asm volatile("ldmatrix.sync.aligned.m8n8.x2.trans.shared.b16 {%0,%1},[%2];"
                 : "=r"(b0), "=r"(b1) : "r"(addr));
}
__device__ __forceinline__ void mma16816(float* c, uint32_t a0, uint32_t a1,
                                         uint32_t a2, uint32_t a3,
                                         uint32_t b0, uint32_t b1) {
    asm volatile(
        "mma.sync.aligned.m16n8k16.row.col.f32.f16.f16.f32 "
        "{%0,%1,%2,%3}, {%4,%5,%6,%7}, {%8,%9}, {%0,%1,%2,%3};"
        : "+f"(c[0]), "+f"(c[1]), "+f"(c[2]), "+f"(c[3])
        : "r"(a0), "r"(a1), "r"(a2), "r"(a3), "r"(b0), "r"(b1));
}
__device__ __forceinline__ uint4 f8_to_h8(float4 f0, float4 f1) {
    __half2 p0 = __floats2half2_rn(f0.x, f0.y), p1 = __floats2half2_rn(f0.z, f0.w);
    __half2 p2 = __floats2half2_rn(f1.x, f1.y), p3 = __floats2half2_rn(f1.z, f1.w);
    uint4 v;
    v.x = *(uint32_t*)&p0; v.y = *(uint32_t*)&p1;
    v.z = *(uint32_t*)&p2; v.w = *(uint32_t*)&p3;
    return v;
}

template <int N, int LAYER>
__global__ __launch_bounds__(256) void k_mma(const float* __restrict__ Xf,
                                             const float* __restrict__ W, int M) {
    constexpr int K  = 128;
    constexpr int UW = N / 8;            // 16B units per W row
    constexpr int NT = N / 16;           // 8-col n-tiles per warp
    __shared__ __align__(16) __half Xs[64 * K];
    __shared__ __align__(16) __half Ws[K * N];

    int tid = threadIdx.x;
    int row0 = blockIdx.x * 64;

    // ---- load W (fp32 -> fp16, swizzled) ----
    #pragma unroll
    for (int t = tid; t < K * UW; t += 256) {
        int r = t / UW, u = t % UW;
        const float4* src = (const float4*)(W + r * N + u * 8);
        uint4 v = f8_to_h8(src[0], src[1]);
        *(uint4*)(Ws + ((r * UW) + (u ^ (r & 7))) * 8) = v;
    }
    // ---- load X tile (swizzled) ----
    if (LAYER == 1) {
        #pragma unroll
        for (int t = tid; t < 64 * 16; t += 256) {
            int r = t / 16, u = t % 16;
            int gr = min(row0 + r, M - 1);
            const float4* src = (const float4*)(Xf + (size_t)gr * K + u * 8);
            uint4 v = f8_to_h8(src[0], src[1]);
            *(uint4*)(Xs + ((r * 16) + (u ^ (r & 7))) * 8) = v;
        }
    } else {
        const uint4* Xh = (const uint4*)g_out1;
        #pragma unroll
        for (int t = tid; t < 64 * 16; t += 256) {
            int r = t / 16, u = t % 16;
            int gr = min(row0 + r, M - 1);
            uint4 v = Xh[(size_t)gr * 16 + u];
            *(uint4*)(Xs + ((r * 16) + (u ^ (r & 7))) * 8) = v;
        }
    }
    __syncthreads();

    int lane = tid & 31, wid = tid >> 5;
    int wm = wid >> 1, wn = wid & 1;

    float acc[NT][4];
    #pragma unroll
    for (int j = 0; j < NT; j++)
        #pragma unroll
        for (int q = 0; q < 4; q++) acc[j][q] = 0.0f;

    int ar = wm * 16 + (lane & 15);
    int asel = lane >> 4;
    int brr = lane & 15;

    #pragma unroll
    for (int ks = 0; ks < 8; ks++) {
        uint32_t a0, a1, a2, a3;
        int uA = ks * 2 + asel;
        ldsm_x4(a0, a1, a2, a3,
                smem_u32(&Xs[((ar * 16) + (uA ^ (ar & 7))) * 8]));
        int rB = ks * 16 + brr;
        #pragma unroll
        for (int j = 0; j < NT; j++) {
            int uB = (wn * (N / 2) + j * 8) >> 3;
            uint32_t b0, b1;
            ldsm_x2t(b0, b1, smem_u32(&Ws[((rB * UW) + (uB ^ (rB & 7))) * 8]));
            mma16816(acc[j], a0, a1, a2, a3, b0, b1);
        }
    }

    // ---- epilogue: *dinv, fp16 store ----
    int r0l = wm * 16 + (lane >> 2);
    int gr0 = row0 + r0l, gr1 = gr0 + 8;
    float dv0 = (gr0 < M) ? g_dinv[gr0] : 0.0f;
    float dv1 = (gr1 < M) ? g_dinv[gr1] : 0.0f;
    __half2* out = (LAYER == 1) ? (__half2*)g_hs1 : (__half2*)g_hs2;
    #pragma unroll
    for (int j = 0; j < NT; j++) {
        int c2 = wn * (N / 4) + j * 4 + (lane & 3);
        if (gr0 < M)
            out[(size_t)gr0 * (N / 2) + c2] =
                __floats2half2_rn(acc[j][0] * dv0, acc[j][1] * dv0);
        if (gr1 < M)
            out[(size_t)gr1 * (N / 2) + c2] =
                __floats2half2_rn(acc[j][2] * dv1, acc[j][3] * dv1);
    }
}

__device__ __forceinline__ void acc_h2(float2& a, __half2 h) {
    float2 f = __half22float2(h);
    a.x += f.x; a.y += f.y;
}

// ---------------- aggregation layer 1 (DIM=128, fp16 in, fp16 out) ----
__global__ __launch_bounds__(256) void k_agg1(const float* __restrict__ bias, int n) {
    const __half2* hs = (const __half2*)g_hs1;   // row = 64 half2
    int warp = (blockIdx.x * blockDim.x + threadIdx.x) >> 5;
    int lane = threadIdx.x & 31;
    if (warp >= n) return;
    int node = warp;

    const __half2* selfp = hs + (size_t)node * 64 + lane;
    float2 a0 = __half22float2(selfp[0]);
    float2 a1 = __half22float2(selfp[32]);

    int e = g_rowptr[node];
    int t = g_rowptr[node + 1];
    for (; e + 4 <= t; e += 4) {
        int c0 = g_col[e], c1 = g_col[e + 1], c2 = g_col[e + 2], c3 = g_col[e + 3];
        const __half2* p0 = hs + (size_t)c0 * 64 + lane;
        const __half2* p1 = hs + (size_t)c1 * 64 + lane;
        const __half2* p2 = hs + (size_t)c2 * 64 + lane;
        const __half2* p3 = hs + (size_t)c3 * 64 + lane;
        __half2 v00 = p0[0], v01 = p0[32];
        __half2 v10 = p1[0], v11 = p1[32];
        __half2 v20 = p2[0], v21 = p2[32];
        __half2 v30 = p3[0], v31 = p3[32];
        acc_h2(a0, v00); acc_h2(a1, v01);
        acc_h2(a0, v10); acc_h2(a1, v11);
        acc_h2(a0, v20); acc_h2(a1, v21);
        acc_h2(a0, v30); acc_h2(a1, v31);
    }
    for (; e < t; e++) {
        const __half2* p0 = hs + (size_t)g_col[e] * 64 + lane;
        acc_h2(a0, p0[0]); acc_h2(a1, p0[32]);
    }

    float dv = g_dinv[node];
    float2 bb0 = ((const float2*)bias)[lane];
    float2 bb1 = ((const float2*)bias)[lane + 32];
    __half2* op = (__half2*)g_out1 + (size_t)node * 64 + lane;
    op[0]  = __floats2half2_rn(fmaxf(fmaf(a0.x, dv, bb0.x), 0.0f),
                               fmaxf(fmaf(a0.y, dv, bb0.y), 0.0f));
    op[32] = __floats2half2_rn(fmaxf(fmaf(a1.x, dv, bb1.x), 0.0f),
                               fmaxf(fmaf(a1.y, dv, bb1.y), 0.0f));
}

// ------- aggregation layer 2 (DIM=64, fp16 in) + fused pool finalize -------
__global__ __launch_bounds__(256) void k_agg2(const float* __restrict__ bias,
                                              const int* __restrict__ batch,
                                              float* __restrict__ out, int n) {
    const __half2* hs = (const __half2*)g_hs2;   // row = 32 half2
    int warp = (blockIdx.x * blockDim.x + threadIdx.x) >> 5;
    int lane = threadIdx.x & 31;
    int node = warp;

    if (node < n) {
        float2 a0 = __half22float2(hs[(size_t)node * 32 + lane]);

        int e = g_rowptr[node];
        int t = g_rowptr[node + 1];
        for (; e + 4 <= t; e += 4) {
            int c0 = g_col[e], c1 = g_col[e + 1], c2 = g_col[e + 2], c3 = g_col[e + 3];
            __half2 v0 = hs[(size_t)c0 * 32 + lane];
            __half2 v1 = hs[(size_t)c1 * 32 + lane];
            __half2 v2 = hs[(size_t)c2 * 32 + lane];
            __half2 v3 = hs[(size_t)c3 * 32 + lane];
            acc_h2(a0, v0); acc_h2(a0, v1); acc_h2(a0, v2); acc_h2(a0, v3);
        }
        for (; e < t; e++)
            acc_h2(a0, hs[(size_t)g_col[e] * 32 + lane]);

        float dv = g_dinv[node];
        float2 bb = ((const float2*)bias)[lane];
        int gidx = batch[node];
        atomicAdd(&g_gsum[gidx * D_OUT + 2 * lane + 0], fmaf(a0.x, dv, bb.x));
        atomicAdd(&g_gsum[gidx * D_OUT + 2 * lane + 1], fmaf(a0.y, dv, bb.y));
    }

    // last-block-done: finalize pool (divide by counts), write output,
    // and re-zero replay state.
    __threadfence();
    __shared__ int is_last;
    if (threadIdx.x == 0) {
        int v = atomicAdd(&g_done, 1);
        is_last = (v == (int)gridDim.x - 1);
    }
    __syncthreads();
    if (is_last) {
        for (int i = threadIdx.x; i < NG * D_OUT; i += blockDim.x) {
            int g = i / D_OUT;
            float c = (float)max(g_gcnt[g], 1);
            out[i] = g_gsum[i] / c;
            g_gsum[i] = 0.0f;
        }
        if (threadIdx.x < NG) g_gcnt[threadIdx.x] = 0;
        if (threadIdx.x == 0) g_done = 0;
    }
}

// ---------------- launch (graph-capturable; no host API calls) ----------
extern "C" void kernel_launch(void* const* d_in, const int* in_sizes, int n_in,
                              void* d_out, int out_size) {
    const float* x = nullptr; const int* ei = nullptr; const int* batch = nullptr;
    const float* W1 = nullptr; const float* b1 = nullptr;
    const float* W2 = nullptr; const float* b2 = nullptr;
    for (int i = 0; i < n_in; i++) {
        switch (in_sizes[i]) {
            case NN * D_IN:      x     = (const float*)d_in[i]; break;
            case 2 * NE:         ei    = (const int*)d_in[i];   break;
            case NN:             batch = (const int*)d_in[i];   break;
            case D_IN * D_HID:   W1    = (const float*)d_in[i]; break;
            case D_HID * D_OUT:  W2    = (const float*)d_in[i]; break;
            case D_HID:          b1    = (const float*)d_in[i]; break;
            case D_OUT:          b2    = (const float*)d_in[i]; break;
        }
    }
    float* out = (float*)d_out;

    const int n = NN, e = NE;
    const int nb256e = (e + 255) / 256;

    k_deg<<<nb256e, 256>>>(ei, batch, e, n);
    k_scan<<<1, 1024>>>(n, e);
    k_fill<<<nb256e, 256>>>(ei, e, n);

    int gb = (n + 63) / 64;               // 782
    k_mma<128, 1><<<gb, 256>>>(x, W1, n);
    k_agg1<<<(n + 7) / 8, 256>>>(b1, n);
    k_mma<64, 2><<<gb, 256>>>(nullptr, W2, n);
    k_agg2<<<(n + 7) / 8, 256>>>(b2, batch, out, n);
}

// round 8
// speedup vs baseline: 1.9338x; 1.9338x over previous
#include <cuda_runtime.h>
#include <cuda_fp16.h>
#include <cstdint>

// Problem constants (fixed by the reference)
#define NN 50000
#define NE 600000
#define NG 64
#define D_IN 128
#define D_HID 128
#define D_OUT 64

// ---------------- device scratch (no allocs allowed) ----------------
// Invariant: g_cnt, g_gsum, g_gcnt are ZERO at entry of every kernel_launch
// call (BSS-zero initially; each run re-zeroes them at the end of k_fill /
// k_final). Keeps the captured graph deterministic across replays.
__device__ __align__(16) int    g_cnt[NN];        // in-degree (edges only)
__device__ __align__(16) float  g_dinv[NN];
__device__ __align__(16) int    g_rowptr[NN + 1];
__device__ __align__(16) int    g_fillptr[NN];
__device__ __align__(16) int    g_bsum[256];
__device__ __align__(16) int    g_boff[256];
__device__ __align__(16) int    g_col[NE];
__device__ __align__(16) __half g_hs1[NN * D_HID];   // (x@W1)*dinv[row], fp16
__device__ __align__(16) __half g_out1[NN * D_HID];  // relu(layer1 agg), fp16
__device__ __align__(16) __half g_hs2[NN * D_OUT];   // (out1@W2)*dinv[row], fp16
__device__ __align__(16) float  g_gsum[NG * D_OUT];
__device__ __align__(16) int    g_gcnt[NG];

// ---------------- degree + graph-size histogram (fused) ----------------
__global__ void k_deg(const int* __restrict__ ei, const int* __restrict__ batch,
                      int e, int n) {
    __shared__ int hist[NG];
    int t = threadIdx.x;
    if (t < NG) hist[t] = 0;
    __syncthreads();
    int i = blockIdx.x * blockDim.x + t;
    if (i < e) atomicAdd(&g_cnt[ei[e + i]], 1);
    if (i < n) atomicAdd(&hist[batch[i]], 1);
    __syncthreads();
    if (t < NG && hist[t]) atomicAdd(&g_gcnt[t], hist[t]);
}

// ---------------- CSR build: 3-kernel parallel scan ----------------
__global__ void k_scan1(int n) {
    __shared__ int s[256];
    int t = threadIdx.x, b = blockIdx.x;
    int i = b * 256 + t;
    int v = (i < n) ? g_cnt[i] : 0;
    s[t] = v;
    __syncthreads();
    #pragma unroll
    for (int off = 1; off < 256; off <<= 1) {
        int add = (t >= off) ? s[t - off] : 0;
        __syncthreads();
        s[t] += add;
        __syncthreads();
    }
    if (i < n) g_rowptr[i] = s[t] - v;       // block-local exclusive
    if (t == 255) g_bsum[b] = s[255];
}

__global__ void k_scan2(int nb) {
    __shared__ int s[256];
    int t = threadIdx.x;
    int v = (t < nb) ? g_bsum[t] : 0;
    s[t] = v;
    __syncthreads();
    #pragma unroll
    for (int off = 1; off < 256; off <<= 1) {
        int add = (t >= off) ? s[t - off] : 0;
        __syncthreads();
        s[t] += add;
        __syncthreads();
    }
    g_boff[t] = s[t] - v;                    // exclusive block offsets
}

// scan finalize + dinv (self-loop folded: deg = cnt + 1)
__global__ void k_scan3(int n, int e) {
    int i = blockIdx.x * blockDim.x + threadIdx.x;
    if (i < n) {
        int val = g_rowptr[i] + g_boff[i >> 8];
        g_rowptr[i] = val;
        g_fillptr[i] = val;
        g_dinv[i] = rsqrtf((float)(g_cnt[i] + 1));
    }
    if (i == 0) g_rowptr[n] = e;
}

// fill CSR cols; re-zero g_cnt for the next replay
__global__ void k_fill(const int* __restrict__ ei, int e, int n) {
    int i = blockIdx.x * blockDim.x + threadIdx.x;
    if (i < e) {
        int s = ei[i];
        int d = ei[e + i];
        int pos = atomicAdd(&g_fillptr[d], 1);
        g_col[pos] = s;
    }
    if (i < n) g_cnt[i] = 0;
}

// ---------------- tensor-core GEMM ----------------
// out[r,:] = half( (X[r,:128] @ W[:128,:N]) * dinv[r] )
// LAYER=1: X = fp32 arg -> g_hs1.  LAYER=2: X = g_out1 (fp16) -> g_hs2.
// BM=64 rows/block, 8 warps tiled 2 (rows) x 4 (cols): each warp owns
// 32 rows x N/4 cols -> per k-step ldmatrix count 16 A + 32 B per block
// (was 8 A + 64 B), cutting shared-load traffic ~33%.
__device__ __forceinline__ uint32_t smem_u32(const void* p) {
    return (uint32_t)__cvta_generic_to_shared(p);
}
__device__ __forceinline__ void ldsm_x4(uint32_t& a0, uint32_t& a1,
                                        uint32_t& a2, uint32_t& a3, uint32_t addr) {
    asm volatile("ldmatrix.sync.aligned.m8n8.x4.shared.b16 {%0,%1,%2,%3},[%4];"
                 : "=r"(a0), "=r"(a1), "=r"(a2), "=r"(a3) : "r"(addr));
}
__device__ __forceinline__ void ldsm_x2t(uint32_t& b0, uint32_t& b1, uint32_t addr) {
    asm volatile("ldmatrix.sync.aligned.m8n8.x2.trans.shared.b16 {%0,%1},[%2];"
                 : "=r"(b0), "=r"(b1) : "r"(addr));
}
__device__ __forceinline__ void mma16816(float* c, uint32_t a0, uint32_t a1,
                                         uint32_t a2, uint32_t a3,
                                         uint32_t b0, uint32_t b1) {
    asm volatile(
        "mma.sync.aligned.m16n8k16.row.col.f32.f16.f16.f32 "
        "{%0,%1,%2,%3}, {%4,%5,%6,%7}, {%8,%9}, {%0,%1,%2,%3};"
        : "+f"(c[0]), "+f"(c[1]), "+f"(c[2]), "+f"(c[3])
        : "r"(a0), "r"(a1), "r"(a2), "r"(a3), "r"(b0), "r"(b1));
}
__device__ __forceinline__ uint4 f8_to_h8(float4 f0, float4 f1) {
    __half2 p0 = __floats2half2_rn(f0.x, f0.y), p1 = __floats2half2_rn(f0.z, f0.w);
    __half2 p2 = __floats2half2_rn(f1.x, f1.y), p3 = __floats2half2_rn(f1.z, f1.w);
    uint4 v;
    v.x = *(uint32_t*)&p0; v.y = *(uint32_t*)&p1;
    v.z = *(uint32_t*)&p2; v.w = *(uint32_t*)&p3;
    return v;
}

template <int N, int LAYER>
__global__ __launch_bounds__(256) void k_mma(const float* __restrict__ Xf,
                                             const float* __restrict__ W, int M) {
    constexpr int K  = 128;
    constexpr int UW = N / 8;            // 16B units per W row
    constexpr int NJ = N / 32;           // 8-col n-tiles per warp (N/4 cols / 8)
    __shared__ __align__(16) __half Xs[64 * K];
    __shared__ __align__(16) __half Ws[K * N];

    int tid = threadIdx.x;
    int row0 = blockIdx.x * 64;

    // ---- load W (fp32 -> fp16, swizzled) ----
    #pragma unroll
    for (int t = tid; t < K * UW; t += 256) {
        int r = t / UW, u = t % UW;
        const float4* src = (const float4*)(W + r * N + u * 8);
        uint4 v = f8_to_h8(src[0], src[1]);
        *(uint4*)(Ws + ((r * UW) + (u ^ (r & 7))) * 8) = v;
    }
    // ---- load X tile (swizzled) ----
    if (LAYER == 1) {
        #pragma unroll
        for (int t = tid; t < 64 * 16; t += 256) {
            int r = t / 16, u = t % 16;
            int gr = min(row0 + r, M - 1);
            const float4* src = (const float4*)(Xf + (size_t)gr * K + u * 8);
            uint4 v = f8_to_h8(src[0], src[1]);
            *(uint4*)(Xs + ((r * 16) + (u ^ (r & 7))) * 8) = v;
        }
    } else {
        const uint4* Xh = (const uint4*)g_out1;
        #pragma unroll
        for (int t = tid; t < 64 * 16; t += 256) {
            int r = t / 16, u = t % 16;
            int gr = min(row0 + r, M - 1);
            uint4 v = Xh[(size_t)gr * 16 + u];
            *(uint4*)(Xs + ((r * 16) + (u ^ (r & 7))) * 8) = v;
        }
    }
    __syncthreads();

    int lane = tid & 31, wid = tid >> 5;
    int wm = wid >> 2;                   // 0..1  (32-row group)
    int wn = wid & 3;                    // 0..3  (N/4-col group)

    float acc[2][NJ][4];
    #pragma unroll
    for (int mt = 0; mt < 2; mt++)
        #pragma unroll
        for (int j = 0; j < NJ; j++)
            #pragma unroll
            for (int q = 0; q < 4; q++) acc[mt][j][q] = 0.0f;

    int asel = lane >> 4;
    int brr = lane & 15;

    #pragma unroll
    for (int ks = 0; ks < 8; ks++) {
        uint32_t a[2][4];
        int uA = ks * 2 + asel;
        #pragma unroll
        for (int mt = 0; mt < 2; mt++) {
            int ar = wm * 32 + mt * 16 + (lane & 15);
            ldsm_x4(a[mt][0], a[mt][1], a[mt][2], a[mt][3],
                    smem_u32(&Xs[((ar * 16) + (uA ^ (ar & 7))) * 8]));
        }
        int rB = ks * 16 + brr;
        #pragma unroll
        for (int j = 0; j < NJ; j++) {
            int uB = wn * (N / 32) + j;          // 16B unit within W row
            uint32_t b0, b1;
            ldsm_x2t(b0, b1, smem_u32(&Ws[((rB * UW) + (uB ^ (rB & 7))) * 8]));
            #pragma unroll
            for (int mt = 0; mt < 2; mt++)
                mma16816(acc[mt][j], a[mt][0], a[mt][1], a[mt][2], a[mt][3], b0, b1);
        }
    }

    // ---- epilogue: *dinv, fp16 store ----
    __half2* out = (LAYER == 1) ? (__half2*)g_hs1 : (__half2*)g_hs2;
    #pragma unroll
    for (int mt = 0; mt < 2; mt++) {
        int gr0 = row0 + wm * 32 + mt * 16 + (lane >> 2);
        int gr1 = gr0 + 8;
        float dv0 = (gr0 < M) ? g_dinv[gr0] : 0.0f;
        float dv1 = (gr1 < M) ? g_dinv[gr1] : 0.0f;
        #pragma unroll
        for (int j = 0; j < NJ; j++) {
            int c2 = wn * (N / 8) + j * 4 + (lane & 3);   // half2 index in row
            if (gr0 < M)
                out[(size_t)gr0 * (N / 2) + c2] =
                    __floats2half2_rn(acc[mt][j][0] * dv0, acc[mt][j][1] * dv0);
            if (gr1 < M)
                out[(size_t)gr1 * (N / 2) + c2] =
                    __floats2half2_rn(acc[mt][j][2] * dv1, acc[mt][j][3] * dv1);
        }
    }
}

__device__ __forceinline__ void acc_h2(float2& a, __half2 h) {
    float2 f = __half22float2(h);
    a.x += f.x; a.y += f.y;
}

// ---------------- aggregation layer 1 (DIM=128, fp16 in, fp16 out) ----
__global__ __launch_bounds__(256) void k_agg1(const float* __restrict__ bias, int n) {
    const __half2* hs = (const __half2*)g_hs1;   // row = 64 half2
    int warp = (blockIdx.x * blockDim.x + threadIdx.x) >> 5;
    int lane = threadIdx.x & 31;
    if (warp >= n) return;
    int node = warp;

    const __half2* selfp = hs + (size_t)node * 64 + lane;
    float2 a0 = __half22float2(selfp[0]);
    float2 a1 = __half22float2(selfp[32]);

    int e = g_rowptr[node];
    int t = g_rowptr[node + 1];
    for (; e + 4 <= t; e += 4) {
        int c0 = g_col[e], c1 = g_col[e + 1], c2 = g_col[e + 2], c3 = g_col[e + 3];
        const __half2* p0 = hs + (size_t)c0 * 64 + lane;
        const __half2* p1 = hs + (size_t)c1 * 64 + lane;
        const __half2* p2 = hs + (size_t)c2 * 64 + lane;
        const __half2* p3 = hs + (size_t)c3 * 64 + lane;
        __half2 v00 = p0[0], v01 = p0[32];
        __half2 v10 = p1[0], v11 = p1[32];
        __half2 v20 = p2[0], v21 = p2[32];
        __half2 v30 = p3[0], v31 = p3[32];
        acc_h2(a0, v00); acc_h2(a1, v01);
        acc_h2(a0, v10); acc_h2(a1, v11);
        acc_h2(a0, v20); acc_h2(a1, v21);
        acc_h2(a0, v30); acc_h2(a1, v31);
    }
    for (; e < t; e++) {
        const __half2* p0 = hs + (size_t)g_col[e] * 64 + lane;
        acc_h2(a0, p0[0]); acc_h2(a1, p0[32]);
    }

    float dv = g_dinv[node];
    float2 bb0 = ((const float2*)bias)[lane];
    float2 bb1 = ((const float2*)bias)[lane + 32];
    __half2* op = (__half2*)g_out1 + (size_t)node * 64 + lane;
    op[0]  = __floats2half2_rn(fmaxf(fmaf(a0.x, dv, bb0.x), 0.0f),
                               fmaxf(fmaf(a0.y, dv, bb0.y), 0.0f));
    op[32] = __floats2half2_rn(fmaxf(fmaf(a1.x, dv, bb1.x), 0.0f),
                               fmaxf(fmaf(a1.y, dv, bb1.y), 0.0f));
}

// ---------------- aggregation layer 2 (DIM=64, fp16 in, pool) ----------
__global__ __launch_bounds__(256) void k_agg2(const float* __restrict__ bias,
                                              const int* __restrict__ batch, int n) {
    const __half2* hs = (const __half2*)g_hs2;   // row = 32 half2
    int warp = (blockIdx.x * blockDim.x + threadIdx.x) >> 5;
    int lane = threadIdx.x & 31;
    if (warp >= n) return;
    int node = warp;

    float2 a0 = __half22float2(hs[(size_t)node * 32 + lane]);

    int e = g_rowptr[node];
    int t = g_rowptr[node + 1];
    for (; e + 4 <= t; e += 4) {
        int c0 = g_col[e], c1 = g_col[e + 1], c2 = g_col[e + 2], c3 = g_col[e + 3];
        __half2 v0 = hs[(size_t)c0 * 32 + lane];
        __half2 v1 = hs[(size_t)c1 * 32 + lane];
        __half2 v2 = hs[(size_t)c2 * 32 + lane];
        __half2 v3 = hs[(size_t)c3 * 32 + lane];
        acc_h2(a0, v0); acc_h2(a0, v1); acc_h2(a0, v2); acc_h2(a0, v3);
    }
    for (; e < t; e++)
        acc_h2(a0, hs[(size_t)g_col[e] * 32 + lane]);

    float dv = g_dinv[node];
    float2 bb = ((const float2*)bias)[lane];
    int gidx = batch[node];
    atomicAdd(&g_gsum[gidx * D_OUT + 2 * lane + 0], fmaf(a0.x, dv, bb.x));
    atomicAdd(&g_gsum[gidx * D_OUT + 2 * lane + 1], fmaf(a0.y, dv, bb.y));
}

// ---------------- final divide + re-zero pool state ----------------
__global__ void k_final(float* __restrict__ out) {
    int i = blockIdx.x * blockDim.x + threadIdx.x;
    if (i < NG * D_OUT) {
        int g = i / D_OUT;
        float c = (float)max(g_gcnt[g], 1);
        out[i] = g_gsum[i] / c;
        g_gsum[i] = 0.0f;
    }
    if (i < NG) g_gcnt[i] = 0;
}

// ---------------- launch (graph-capturable; no host API calls) ----------
extern "C" void kernel_launch(void* const* d_in, const int* in_sizes, int n_in,
                              void* d_out, int out_size) {
    const float* x = nullptr; const int* ei = nullptr; const int* batch = nullptr;
    const float* W1 = nullptr; const float* b1 = nullptr;
    const float* W2 = nullptr; const float* b2 = nullptr;
    for (int i = 0; i < n_in; i++) {
        switch (in_sizes[i]) {
            case NN * D_IN:      x     = (const float*)d_in[i]; break;
            case 2 * NE:         ei    = (const int*)d_in[i];   break;
            case NN:             batch = (const int*)d_in[i];   break;
            case D_IN * D_HID:   W1    = (const float*)d_in[i]; break;
            case D_HID * D_OUT:  W2    = (const float*)d_in[i]; break;
            case D_HID:          b1    = (const float*)d_in[i]; break;
            case D_OUT:          b2    = (const float*)d_in[i]; break;
        }
    }
    float* out = (float*)d_out;

    const int n = NN, e = NE;
    const int nb256n = (n + 255) / 256;   // 196
    const int nb256e = (e + 255) / 256;

    k_deg<<<nb256e, 256>>>(ei, batch, e, n);
    k_scan1<<<nb256n, 256>>>(n);
    k_scan2<<<1, 256>>>(nb256n);
    k_scan3<<<nb256n, 256>>>(n, e);
    k_fill<<<nb256e, 256>>>(ei, e, n);

    int gb = (n + 63) / 64;               // 782
    k_mma<128, 1><<<gb, 256>>>(x, W1, n);
    k_agg1<<<(n + 7) / 8, 256>>>(b1, n);
    k_mma<64, 2><<<gb, 256>>>(nullptr, W2, n);
    k_agg2<<<(n + 7) / 8, 256>>>(b2, batch, n);
    k_final<<<(NG * D_OUT + 255) / 256, 256>>>(out);
}

// round 9
// speedup vs baseline: 1.9959x; 1.0321x over previous
#include <cuda_runtime.h>
#include <cuda_fp16.h>
#include <cstdint>

// Problem constants (fixed by the reference)
#define NN 50000
#define NE 600000
#define NG 64
#define D_IN 128
#define D_HID 128
#define D_OUT 64

// ---------------- device scratch (no allocs allowed) ----------------
// Invariant: g_cnt, g_gsum, g_gcnt are ZERO at entry of every kernel_launch
// call (BSS-zero initially; re-zeroed at the end of k_fill / k_final).
__device__ __align__(16) int    g_cnt[NN];        // in-degree (edges only)
__device__ __align__(16) float  g_dinv[NN];
__device__ __align__(16) int    g_rowptr[NN + 1];
__device__ __align__(16) int    g_fillptr[NN];
__device__ __align__(16) int    g_bsum[256];
__device__ __align__(16) int    g_col[NE];
__device__ __align__(16) __half g_w1h[D_IN * D_HID];   // fp16 W1
__device__ __align__(16) __half g_w2h[D_HID * D_OUT];  // fp16 W2
__device__ __align__(16) __half g_hs1[NN * D_HID];   // (x@W1)*dinv[row], fp16
__device__ __align__(16) __half g_out1[NN * D_HID];  // relu(layer1 agg), fp16
__device__ __align__(16) __half g_hs2[NN * D_OUT];   // (out1@W2)*dinv[row], fp16
__device__ __align__(16) float  g_gsum[NG * D_OUT];
__device__ __align__(16) int    g_gcnt[NG];

// ------- degree + graph histogram + W fp16 pre-convert (all fused) -------
__global__ void k_deg(const int* __restrict__ ei, const int* __restrict__ batch,
                      const float* __restrict__ W1, const float* __restrict__ W2,
                      int e, int n) {
    __shared__ int hist[NG];
    int t = threadIdx.x;
    if (t < NG) hist[t] = 0;
    __syncthreads();
    int i = blockIdx.x * blockDim.x + t;
    if (i < e) atomicAdd(&g_cnt[ei[e + i]], 1);
    if (i < n) atomicAdd(&hist[batch[i]], 1);
    // W pre-convert (vectorized float2 -> half2)
    if (i < (D_IN * D_HID) / 2) {
        float2 v = ((const float2*)W1)[i];
        ((__half2*)g_w1h)[i] = __floats2half2_rn(v.x, v.y);
    }
    if (i < (D_HID * D_OUT) / 2) {
        float2 v = ((const float2*)W2)[i];
        ((__half2*)g_w2h)[i] = __floats2half2_rn(v.x, v.y);
    }
    __syncthreads();
    if (t < NG && hist[t]) atomicAdd(&g_gcnt[t], hist[t]);
}

// ---------------- CSR build: 2-kernel parallel scan ----------------
__global__ void k_scan1(int n) {
    __shared__ int s[256];
    int t = threadIdx.x, b = blockIdx.x;
    int i = b * 256 + t;
    int v = (i < n) ? g_cnt[i] : 0;
    s[t] = v;
    __syncthreads();
    #pragma unroll
    for (int off = 1; off < 256; off <<= 1) {
        int add = (t >= off) ? s[t - off] : 0;
        __syncthreads();
        s[t] += add;
        __syncthreads();
    }
    if (i < n) g_rowptr[i] = s[t] - v;       // block-local exclusive
    if (t == 255) g_bsum[b] = s[255];
}

// finalize: every block redundantly scans the 196 block sums in smem
// (cheap), then applies its own offset. Also computes dinv. Replaces the
// old separate single-block k_scan2.
__global__ void k_scan3(int n, int e, int nb) {
    __shared__ int s[256];
    int t = threadIdx.x, b = blockIdx.x;
    int v = (t < nb) ? g_bsum[t] : 0;
    s[t] = v;
    __syncthreads();
    #pragma unroll
    for (int off = 1; off < 256; off <<= 1) {
        int add = (t >= off) ? s[t - off] : 0;
        __syncthreads();
        s[t] += add;
        __syncthreads();
    }
    int boff = (b == 0) ? 0 : s[b - 1];      // exclusive offset of this block

    int i = b * 256 + t;
    if (i < n) {
        int val = g_rowptr[i] + boff;
        g_rowptr[i] = val;
        g_fillptr[i] = val;
        g_dinv[i] = rsqrtf((float)(g_cnt[i] + 1));   // self-loop folded
    }
    if (i == 0) g_rowptr[n] = e;
}

// fill CSR cols; re-zero g_cnt for the next replay
__global__ void k_fill(const int* __restrict__ ei, int e, int n) {
    int i = blockIdx.x * blockDim.x + threadIdx.x;
    if (i < e) {
        int s = ei[i];
        int d = ei[e + i];
        int pos = atomicAdd(&g_fillptr[d], 1);
        g_col[pos] = s;
    }
    if (i < n) g_cnt[i] = 0;
}

// ---------------- tensor-core GEMM ----------------
// out[r,:] = half( (X[r,:128] @ W[:128,:N]) * dinv[r] )
// LAYER=1: X = fp32 arg, W = g_w1h -> g_hs1.
// LAYER=2: X = g_out1 (fp16), W = g_w2h -> g_hs2.
__device__ __forceinline__ uint32_t smem_u32(const void* p) {
    return (uint32_t)__cvta_generic_to_shared(p);
}
__device__ __forceinline__ void ldsm_x4(uint32_t& a0, uint32_t& a1,
                                        uint32_t& a2, uint32_t& a3, uint32_t addr) {
    asm volatile("ldmatrix.sync.aligned.m8n8.x4.shared.b16 {%0,%1,%2,%3},[%4];"
                 : "=r"(a0), "=r"(a1), "=r"(a2), "=r"(a3) : "r"(addr));
}
__device__ __forceinline__ void ldsm_x2t(uint32_t& b0, uint32_t& b1, uint32_t addr) {
    asm volatile("ldmatrix.sync.aligned.m8n8.x2.trans.shared.b16 {%0,%1},[%2];"
                 : "=r"(b0), "=r"(b1) : "r"(addr));
}
__device__ __forceinline__ void mma16816(float* c, uint32_t a0, uint32_t a1,
                                         uint32_t a2, uint32_t a3,
                                         uint32_t b0, uint32_t b1) {
    asm volatile(
        "mma.sync.aligned.m16n8k16.row.col.f32.f16.f16.f32 "
        "{%0,%1,%2,%3}, {%4,%5,%6,%7}, {%8,%9}, {%0,%1,%2,%3};"
        : "+f"(c[0]), "+f"(c[1]), "+f"(c[2]), "+f"(c[3])
        : "r"(a0), "r"(a1), "r"(a2), "r"(a3), "r"(b0), "r"(b1));
}
__device__ __forceinline__ uint4 f8_to_h8(float4 f0, float4 f1) {
    __half2 p0 = __floats2half2_rn(f0.x, f0.y), p1 = __floats2half2_rn(f0.z, f0.w);
    __half2 p2 = __floats2half2_rn(f1.x, f1.y), p3 = __floats2half2_rn(f1.z, f1.w);
    uint4 v;
    v.x = *(uint32_t*)&p0; v.y = *(uint32_t*)&p1;
    v.z = *(uint32_t*)&p2; v.w = *(uint32_t*)&p3;
    return v;
}

template <int N, int LAYER>
__global__ __launch_bounds__(256) void k_mma(const float* __restrict__ Xf, int M) {
    constexpr int K  = 128;
    constexpr int UW = N / 8;            // 16B units per W row
    constexpr int NJ = N / 32;           // 8-col n-tiles per warp
    __shared__ __align__(16) __half Xs[64 * K];
    __shared__ __align__(16) __half Ws[K * N];

    int tid = threadIdx.x;
    int row0 = blockIdx.x * 64;

    // ---- load W (fp16 source, swizzled copy) ----
    const uint4* Wh = (const uint4*)((LAYER == 1) ? g_w1h : g_w2h);
    #pragma unroll
    for (int t = tid; t < K * UW; t += 256) {
        int r = t / UW, u = t % UW;
        *(uint4*)(Ws + ((r * UW) + (u ^ (r & 7))) * 8) = Wh[r * UW + u];
    }
    // ---- load X tile (swizzled) ----
    if (LAYER == 1) {
        #pragma unroll
        for (int t = tid; t < 64 * 16; t += 256) {
            int r = t / 16, u = t % 16;
            int gr = min(row0 + r, M - 1);
            const float4* src = (const float4*)(Xf + (size_t)gr * K + u * 8);
            uint4 v = f8_to_h8(src[0], src[1]);
            *(uint4*)(Xs + ((r * 16) + (u ^ (r & 7))) * 8) = v;
        }
    } else {
        const uint4* Xh = (const uint4*)g_out1;
        #pragma unroll
        for (int t = tid; t < 64 * 16; t += 256) {
            int r = t / 16, u = t % 16;
            int gr = min(row0 + r, M - 1);
            uint4 v = Xh[(size_t)gr * 16 + u];
            *(uint4*)(Xs + ((r * 16) + (u ^ (r & 7))) * 8) = v;
        }
    }
    __syncthreads();

    int lane = tid & 31, wid = tid >> 5;
    int wm = wid >> 2;                   // 0..1  (32-row group)
    int wn = wid & 3;                    // 0..3  (N/4-col group)

    float acc[2][NJ][4];
    #pragma unroll
    for (int mt = 0; mt < 2; mt++)
        #pragma unroll
        for (int j = 0; j < NJ; j++)
            #pragma unroll
            for (int q = 0; q < 4; q++) acc[mt][j][q] = 0.0f;

    int asel = lane >> 4;
    int brr = lane & 15;

    #pragma unroll
    for (int ks = 0; ks < 8; ks++) {
        uint32_t a[2][4];
        int uA = ks * 2 + asel;
        #pragma unroll
        for (int mt = 0; mt < 2; mt++) {
            int ar = wm * 32 + mt * 16 + (lane & 15);
            ldsm_x4(a[mt][0], a[mt][1], a[mt][2], a[mt][3],
                    smem_u32(&Xs[((ar * 16) + (uA ^ (ar & 7))) * 8]));
        }
        int rB = ks * 16 + brr;
        #pragma unroll
        for (int j = 0; j < NJ; j++) {
            int uB = wn * (N / 32) + j;
            uint32_t b0, b1;
            ldsm_x2t(b0, b1, smem_u32(&Ws[((rB * UW) + (uB ^ (rB & 7))) * 8]));
            #pragma unroll
            for (int mt = 0; mt < 2; mt++)
                mma16816(acc[mt][j], a[mt][0], a[mt][1], a[mt][2], a[mt][3], b0, b1);
        }
    }

    // ---- epilogue: *dinv, fp16 store ----
    __half2* out = (LAYER == 1) ? (__half2*)g_hs1 : (__half2*)g_hs2;
    #pragma unroll
    for (int mt = 0; mt < 2; mt++) {
        int gr0 = row0 + wm * 32 + mt * 16 + (lane >> 2);
        int gr1 = gr0 + 8;
        float dv0 = (gr0 < M) ? g_dinv[gr0] : 0.0f;
        float dv1 = (gr1 < M) ? g_dinv[gr1] : 0.0f;
        #pragma unroll
        for (int j = 0; j < NJ; j++) {
            int c2 = wn * (N / 8) + j * 4 + (lane & 3);
            if (gr0 < M)
                out[(size_t)gr0 * (N / 2) + c2] =
                    __floats2half2_rn(acc[mt][j][0] * dv0, acc[mt][j][1] * dv0);
            if (gr1 < M)
                out[(size_t)gr1 * (N / 2) + c2] =
                    __floats2half2_rn(acc[mt][j][2] * dv1, acc[mt][j][3] * dv1);
        }
    }
}

__device__ __forceinline__ void acc_u2(float2& a0, float2& a1, uint2 v) {
    float2 f0 = __half22float2(*(__half2*)&v.x);
    float2 f1 = __half22float2(*(__half2*)&v.y);
    a0.x += f0.x; a0.y += f0.y;
    a1.x += f1.x; a1.y += f1.y;
}

// ---------------- aggregation layer 1 (DIM=128, fp16 in/out) ----------
// One uint2 (8B) load per lane per neighbor row: lane covers cols 4l..4l+3.
__global__ __launch_bounds__(256) void k_agg1(const float* __restrict__ bias, int n) {
    const uint2* hs = (const uint2*)g_hs1;   // row = 32 uint2
    int warp = (blockIdx.x * blockDim.x + threadIdx.x) >> 5;
    int lane = threadIdx.x & 31;
    if (warp >= n) return;
    int node = warp;

    float2 a0 = {0.f, 0.f}, a1 = {0.f, 0.f};
    acc_u2(a0, a1, hs[(size_t)node * 32 + lane]);   // self

    int e = g_rowptr[node];
    int t = g_rowptr[node + 1];
    for (; e + 4 <= t; e += 4) {
        int c0 = g_col[e], c1 = g_col[e + 1], c2 = g_col[e + 2], c3 = g_col[e + 3];
        uint2 v0 = hs[(size_t)c0 * 32 + lane];
        uint2 v1 = hs[(size_t)c1 * 32 + lane];
        uint2 v2 = hs[(size_t)c2 * 32 + lane];
        uint2 v3 = hs[(size_t)c3 * 32 + lane];
        acc_u2(a0, a1, v0); acc_u2(a0, a1, v1);
        acc_u2(a0, a1, v2); acc_u2(a0, a1, v3);
    }
    for (; e < t; e++)
        acc_u2(a0, a1, hs[(size_t)g_col[e] * 32 + lane]);

    float dv = g_dinv[node];
    float4 bb = ((const float4*)bias)[lane];   // cols 4l..4l+3
    __half2 o0 = __floats2half2_rn(fmaxf(fmaf(a0.x, dv, bb.x), 0.0f),
                                   fmaxf(fmaf(a0.y, dv, bb.y), 0.0f));
    __half2 o1 = __floats2half2_rn(fmaxf(fmaf(a1.x, dv, bb.z), 0.0f),
                                   fmaxf(fmaf(a1.y, dv, bb.w), 0.0f));
    uint2 st;
    st.x = *(uint32_t*)&o0; st.y = *(uint32_t*)&o1;
    ((uint2*)g_out1)[(size_t)node * 32 + lane] = st;
}

__device__ __forceinline__ void acc_h2(float2& a, __half2 h) {
    float2 f = __half22float2(h);
    a.x += f.x; a.y += f.y;
}

// ---------------- aggregation layer 2 (DIM=64, fp16 in, pool) ----------
__global__ __launch_bounds__(256) void k_agg2(const float* __restrict__ bias,
                                              const int* __restrict__ batch, int n) {
    const __half2* hs = (const __half2*)g_hs2;   // row = 32 half2
    int warp = (blockIdx.x * blockDim.x + threadIdx.x) >> 5;
    int lane = threadIdx.x & 31;
    if (warp >= n) return;
    int node = warp;

    float2 a0 = __half22float2(hs[(size_t)node * 32 + lane]);

    int e = g_rowptr[node];
    int t = g_rowptr[node + 1];
    for (; e + 4 <= t; e += 4) {
        int c0 = g_col[e], c1 = g_col[e + 1], c2 = g_col[e + 2], c3 = g_col[e + 3];
        __half2 v0 = hs[(size_t)c0 * 32 + lane];
        __half2 v1 = hs[(size_t)c1 * 32 + lane];
        __half2 v2 = hs[(size_t)c2 * 32 + lane];
        __half2 v3 = hs[(size_t)c3 * 32 + lane];
        acc_h2(a0, v0); acc_h2(a0, v1); acc_h2(a0, v2); acc_h2(a0, v3);
    }
    for (; e < t; e++)
        acc_h2(a0, hs[(size_t)g_col[e] * 32 + lane]);

    float dv = g_dinv[node];
    float2 bb = ((const float2*)bias)[lane];
    int gidx = batch[node];
    atomicAdd(&g_gsum[gidx * D_OUT + 2 * lane + 0], fmaf(a0.x, dv, bb.x));
    atomicAdd(&g_gsum[gidx * D_OUT + 2 * lane + 1], fmaf(a0.y, dv, bb.y));
}

// ---------------- final divide + re-zero pool state ----------------
__global__ void k_final(float* __restrict__ out) {
    int i = blockIdx.x * blockDim.x + threadIdx.x;
    if (i < NG * D_OUT) {
        int g = i / D_OUT;
        float c = (float)max(g_gcnt[g], 1);
        out[i] = g_gsum[i] / c;
        g_gsum[i] = 0.0f;
    }
    if (i < NG) g_gcnt[i] = 0;
}

// ---------------- launch (graph-capturable; no host API calls) ----------
extern "C" void kernel_launch(void* const* d_in, const int* in_sizes, int n_in,
                              void* d_out, int out_size) {
    const float* x = nullptr; const int* ei = nullptr; const int* batch = nullptr;
    const float* W1 = nullptr; const float* b1 = nullptr;
    const float* W2 = nullptr; const float* b2 = nullptr;
    for (int i = 0; i < n_in; i++) {
        switch (in_sizes[i]) {
            case NN * D_IN:      x     = (const float*)d_in[i]; break;
            case 2 * NE:         ei    = (const int*)d_in[i];   break;
            case NN:             batch = (const int*)d_in[i];   break;
            case D_IN * D_HID:   W1    = (const float*)d_in[i]; break;
            case D_HID * D_OUT:  W2    = (const float*)d_in[i]; break;
            case D_HID:          b1    = (const float*)d_in[i]; break;
            case D_OUT:          b2    = (const float*)d_in[i]; break;
        }
    }
    float* out = (float*)d_out;

    const int n = NN, e = NE;
    const int nb256n = (n + 255) / 256;   // 196
    const int nb256e = (e + 255) / 256;

    k_deg<<<nb256e, 256>>>(ei, batch, W1, W2, e, n);
    k_scan1<<<nb256n, 256>>>(n);
    k_scan3<<<nb256n, 256>>>(n, e, nb256n);
    k_fill<<<nb256e, 256>>>(ei, e, n);

    int gb = (n + 63) / 64;               // 782
    k_mma<128, 1><<<gb, 256>>>(x, n);
    k_agg1<<<(n + 7) / 8, 256>>>(b1, n);
    k_mma<64, 2><<<gb, 256>>>(nullptr, n);
    k_agg2<<<(n + 7) / 8, 256>>>(b2, batch, n);
    k_final<<<(NG * D_OUT + 255) / 256, 256>>>(out);
}

// round 10
// speedup vs baseline: 2.0201x; 1.0121x over previous
#include <cuda_runtime.h>
#include <cuda_fp16.h>
#include <cstdint>

// Problem constants (fixed by the reference)
#define NN 50000
#define NE 600000
#define NG 64
#define D_IN 128
#define D_HID 128
#define D_OUT 64

// ---------------- device scratch (no allocs allowed) ----------------
// Invariant: g_cnt, g_gsum, g_gcnt are ZERO at entry of every kernel_launch
// call (BSS-zero initially; re-zeroed at the end of k_fill / k_final).
__device__ __align__(16) int    g_cnt[NN];        // in-degree (edges only)
__device__ __align__(16) float  g_dinv[NN];
__device__ __align__(16) int    g_rowptr[NN + 1];
__device__ __align__(16) int    g_fillptr[NN];
__device__ __align__(16) int    g_bsum[256];
__device__ __align__(16) int    g_col[NE];
__device__ __align__(16) __half g_w1h[D_IN * D_HID];   // fp16 W1
__device__ __align__(16) __half g_w2h[D_HID * D_OUT];  // fp16 W2
__device__ __align__(16) __half g_hs1[NN * D_HID];   // (x@W1)*dinv[row], fp16
__device__ __align__(16) __half g_out1[NN * D_HID];  // relu(layer1 agg), fp16
__device__ __align__(16) __half g_hs2[NN * D_OUT];   // (out1@W2)*dinv[row], fp16
__device__ __align__(16) float  g_gsum[NG * D_OUT];
__device__ __align__(16) int    g_gcnt[NG];

// ------- degree (4 edges/thread) + graph histogram + W fp16 convert -------
__global__ void k_deg(const int* __restrict__ ei, const int* __restrict__ batch,
                      const float* __restrict__ W1, const float* __restrict__ W2,
                      int e4, int n) {
    __shared__ int hist[NG];
    int t = threadIdx.x;
    if (t < NG) hist[t] = 0;
    __syncthreads();
    int i = blockIdx.x * blockDim.x + t;
    if (i < e4) {                         // 4 dst indices, one 16B load
        int4 d = ((const int4*)ei)[e4 + i];   // dst row starts at element e=4*e4
        atomicAdd(&g_cnt[d.x], 1);
        atomicAdd(&g_cnt[d.y], 1);
        atomicAdd(&g_cnt[d.z], 1);
        atomicAdd(&g_cnt[d.w], 1);
    }
    if (i < n) atomicAdd(&hist[batch[i]], 1);
    // W pre-convert (vectorized float2 -> half2)
    if (i < (D_IN * D_HID) / 2) {
        float2 v = ((const float2*)W1)[i];
        ((__half2*)g_w1h)[i] = __floats2half2_rn(v.x, v.y);
    }
    if (i < (D_HID * D_OUT) / 2) {
        float2 v = ((const float2*)W2)[i];
        ((__half2*)g_w2h)[i] = __floats2half2_rn(v.x, v.y);
    }
    __syncthreads();
    if (t < NG && hist[t]) atomicAdd(&g_gcnt[t], hist[t]);
}

// ---------------- CSR build: 2-kernel parallel scan ----------------
__global__ void k_scan1(int n) {
    __shared__ int s[256];
    int t = threadIdx.x, b = blockIdx.x;
    int i = b * 256 + t;
    int v = (i < n) ? g_cnt[i] : 0;
    s[t] = v;
    __syncthreads();
    #pragma unroll
    for (int off = 1; off < 256; off <<= 1) {
        int add = (t >= off) ? s[t - off] : 0;
        __syncthreads();
        s[t] += add;
        __syncthreads();
    }
    if (i < n) g_rowptr[i] = s[t] - v;       // block-local exclusive
    if (t == 255) g_bsum[b] = s[255];
}

// finalize: every block redundantly scans the 196 block sums in smem
// (cheap), then applies its own offset. Also computes dinv.
__global__ void k_scan3(int n, int e, int nb) {
    __shared__ int s[256];
    int t = threadIdx.x, b = blockIdx.x;
    int v = (t < nb) ? g_bsum[t] : 0;
    s[t] = v;
    __syncthreads();
    #pragma unroll
    for (int off = 1; off < 256; off <<= 1) {
        int add = (t >= off) ? s[t - off] : 0;
        __syncthreads();
        s[t] += add;
        __syncthreads();
    }
    int boff = (b == 0) ? 0 : s[b - 1];      // exclusive offset of this block

    int i = b * 256 + t;
    if (i < n) {
        int val = g_rowptr[i] + boff;
        g_rowptr[i] = val;
        g_fillptr[i] = val;
        g_dinv[i] = rsqrtf((float)(g_cnt[i] + 1));   // self-loop folded
    }
    if (i == 0) g_rowptr[n] = e;
}

// fill CSR cols (4 edges/thread); re-zero g_cnt for the next replay
__global__ void k_fill(const int* __restrict__ ei, int e4, int n) {
    int i = blockIdx.x * blockDim.x + threadIdx.x;
    if (i < e4) {
        int4 s = ((const int4*)ei)[i];        // 4 src
        int4 d = ((const int4*)ei)[e4 + i];   // 4 dst
        int p0 = atomicAdd(&g_fillptr[d.x], 1);
        int p1 = atomicAdd(&g_fillptr[d.y], 1);
        int p2 = atomicAdd(&g_fillptr[d.z], 1);
        int p3 = atomicAdd(&g_fillptr[d.w], 1);
        g_col[p0] = s.x;
        g_col[p1] = s.y;
        g_col[p2] = s.z;
        g_col[p3] = s.w;
    }
    if (i < n) g_cnt[i] = 0;
}

// ---------------- tensor-core GEMM ----------------
// out[r,:] = half( (X[r,:128] @ W[:128,:N]) * dinv[r] )
// LAYER=1: X = fp32 arg, W = g_w1h -> g_hs1.
// LAYER=2: X = g_out1 (fp16), W = g_w2h -> g_hs2.
__device__ __forceinline__ uint32_t smem_u32(const void* p) {
    return (uint32_t)__cvta_generic_to_shared(p);
}
__device__ __forceinline__ void ldsm_x4(uint32_t& a0, uint32_t& a1,
                                        uint32_t& a2, uint32_t& a3, uint32_t addr) {
    asm volatile("ldmatrix.sync.aligned.m8n8.x4.shared.b16 {%0,%1,%2,%3},[%4];"
                 : "=r"(a0), "=r"(a1), "=r"(a2), "=r"(a3) : "r"(addr));
}
__device__ __forceinline__ void ldsm_x2t(uint32_t& b0, uint32_t& b1, uint32_t addr) {
    asm volatile("ldmatrix.sync.aligned.m8n8.x2.trans.shared.b16 {%0,%1},[%2];"
                 : "=r"(b0), "=r"(b1) : "r"(addr));
}
__device__ __forceinline__ void mma16816(float* c, uint32_t a0, uint32_t a1,
                                         uint32_t a2, uint32_t a3,
                                         uint32_t b0, uint32_t b1) {
    asm volatile(
        "mma.sync.aligned.m16n8k16.row.col.f32.f16.f16.f32 "
        "{%0,%1,%2,%3}, {%4,%5,%6,%7}, {%8,%9}, {%0,%1,%2,%3};"
        : "+f"(c[0]), "+f"(c[1]), "+f"(c[2]), "+f"(c[3])
        : "r"(a0), "r"(a1), "r"(a2), "r"(a3), "r"(b0), "r"(b1));
}
__device__ __forceinline__ uint4 f8_to_h8(float4 f0, float4 f1) {
    __half2 p0 = __floats2half2_rn(f0.x, f0.y), p1 = __floats2half2_rn(f0.z, f0.w);
    __half2 p2 = __floats2half2_rn(f1.x, f1.y), p3 = __floats2half2_rn(f1.z, f1.w);
    uint4 v;
    v.x = *(uint32_t*)&p0; v.y = *(uint32_t*)&p1;
    v.z = *(uint32_t*)&p2; v.w = *(uint32_t*)&p3;
    return v;
}

template <int N, int LAYER>
__global__ __launch_bounds__(256) void k_mma(const float* __restrict__ Xf, int M) {
    constexpr int K  = 128;
    constexpr int UW = N / 8;            // 16B units per W row
    constexpr int NJ = N / 32;           // 8-col n-tiles per warp
    __shared__ __align__(16) __half Xs[64 * K];
    __shared__ __align__(16) __half Ws[K * N];

    int tid = threadIdx.x;
    int row0 = blockIdx.x * 64;

    // ---- load W (fp16 source, swizzled copy) ----
    const uint4* Wh = (const uint4*)((LAYER == 1) ? g_w1h : g_w2h);
    #pragma unroll
    for (int t = tid; t < K * UW; t += 256) {
        int r = t / UW, u = t % UW;
        *(uint4*)(Ws + ((r * UW) + (u ^ (r & 7))) * 8) = Wh[r * UW + u];
    }
    // ---- load X tile (swizzled) ----
    if (LAYER == 1) {
        #pragma unroll
        for (int t = tid; t < 64 * 16; t += 256) {
            int r = t / 16, u = t % 16;
            int gr = min(row0 + r, M - 1);
            const float4* src = (const float4*)(Xf + (size_t)gr * K + u * 8);
            uint4 v = f8_to_h8(src[0], src[1]);
            *(uint4*)(Xs + ((r * 16) + (u ^ (r & 7))) * 8) = v;
        }
    } else {
        const uint4* Xh = (const uint4*)g_out1;
        #pragma unroll
        for (int t = tid; t < 64 * 16; t += 256) {
            int r = t / 16, u = t % 16;
            int gr = min(row0 + r, M - 1);
            uint4 v = Xh[(size_t)gr * 16 + u];
            *(uint4*)(Xs + ((r * 16) + (u ^ (r & 7))) * 8) = v;
        }
    }
    __syncthreads();

    int lane = tid & 31, wid = tid >> 5;
    int wm = wid >> 2;                   // 0..1  (32-row group)
    int wn = wid & 3;                    // 0..3  (N/4-col group)

    float acc[2][NJ][4];
    #pragma unroll
    for (int mt = 0; mt < 2; mt++)
        #pragma unroll
        for (int j = 0; j < NJ; j++)
            #pragma unroll
            for (int q = 0; q < 4; q++) acc[mt][j][q] = 0.0f;

    int asel = lane >> 4;
    int brr = lane & 15;

    #pragma unroll
    for (int ks = 0; ks < 8; ks++) {
        uint32_t a[2][4];
        int uA = ks * 2 + asel;
        #pragma unroll
        for (int mt = 0; mt < 2; mt++) {
            int ar = wm * 32 + mt * 16 + (lane & 15);
            ldsm_x4(a[mt][0], a[mt][1], a[mt][2], a[mt][3],
                    smem_u32(&Xs[((ar * 16) + (uA ^ (ar & 7))) * 8]));
        }
        int rB = ks * 16 + brr;
        #pragma unroll
        for (int j = 0; j < NJ; j++) {
            int uB = wn * (N / 32) + j;
            uint32_t b0, b1;
            ldsm_x2t(b0, b1, smem_u32(&Ws[((rB * UW) + (uB ^ (rB & 7))) * 8]));
            #pragma unroll
            for (int mt = 0; mt < 2; mt++)
                mma16816(acc[mt][j], a[mt][0], a[mt][1], a[mt][2], a[mt][3], b0, b1);
        }
    }

    // ---- epilogue: *dinv, fp16 store ----
    __half2* out = (LAYER == 1) ? (__half2*)g_hs1 : (__half2*)g_hs2;
    #pragma unroll
    for (int mt = 0; mt < 2; mt++) {
        int gr0 = row0 + wm * 32 + mt * 16 + (lane >> 2);
        int gr1 = gr0 + 8;
        float dv0 = (gr0 < M) ? g_dinv[gr0] : 0.0f;
        float dv1 = (gr1 < M) ? g_dinv[gr1] : 0.0f;
        #pragma unroll
        for (int j = 0; j < NJ; j++) {
            int c2 = wn * (N / 8) + j * 4 + (lane & 3);
            if (gr0 < M)
                out[(size_t)gr0 * (N / 2) + c2] =
                    __floats2half2_rn(acc[mt][j][0] * dv0, acc[mt][j][1] * dv0);
            if (gr1 < M)
                out[(size_t)gr1 * (N / 2) + c2] =
                    __floats2half2_rn(acc[mt][j][2] * dv1, acc[mt][j][3] * dv1);
        }
    }
}

__device__ __forceinline__ void acc_u2(float2& a0, float2& a1, uint2 v) {
    float2 f0 = __half22float2(*(__half2*)&v.x);
    float2 f1 = __half22float2(*(__half2*)&v.y);
    a0.x += f0.x; a0.y += f0.y;
    a1.x += f1.x; a1.y += f1.y;
}

// ---------------- aggregation layer 1 (DIM=128, fp16 in/out) ----------
// One uint2 (8B) load per lane per neighbor row: lane covers cols 4l..4l+3.
__global__ __launch_bounds__(256) void k_agg1(const float* __restrict__ bias, int n) {
    const uint2* hs = (const uint2*)g_hs1;   // row = 32 uint2
    int warp = (blockIdx.x * blockDim.x + threadIdx.x) >> 5;
    int lane = threadIdx.x & 31;
    if (warp >= n) return;
    int node = warp;

    float2 a0 = {0.f, 0.f}, a1 = {0.f, 0.f};
    acc_u2(a0, a1, hs[(size_t)node * 32 + lane]);   // self

    int e = g_rowptr[node];
    int t = g_rowptr[node + 1];
    for (; e + 4 <= t; e += 4) {
        int c0 = g_col[e], c1 = g_col[e + 1], c2 = g_col[e + 2], c3 = g_col[e + 3];
        uint2 v0 = hs[(size_t)c0 * 32 + lane];
        uint2 v1 = hs[(size_t)c1 * 32 + lane];
        uint2 v2 = hs[(size_t)c2 * 32 + lane];
        uint2 v3 = hs[(size_t)c3 * 32 + lane];
        acc_u2(a0, a1, v0); acc_u2(a0, a1, v1);
        acc_u2(a0, a1, v2); acc_u2(a0, a1, v3);
    }
    for (; e < t; e++)
        acc_u2(a0, a1, hs[(size_t)g_col[e] * 32 + lane]);

    float dv = g_dinv[node];
    float4 bb = ((const float4*)bias)[lane];   // cols 4l..4l+3
    __half2 o0 = __floats2half2_rn(fmaxf(fmaf(a0.x, dv, bb.x), 0.0f),
                                   fmaxf(fmaf(a0.y, dv, bb.y), 0.0f));
    __half2 o1 = __floats2half2_rn(fmaxf(fmaf(a1.x, dv, bb.z), 0.0f),
                                   fmaxf(fmaf(a1.y, dv, bb.w), 0.0f));
    uint2 st;
    st.x = *(uint32_t*)&o0; st.y = *(uint32_t*)&o1;
    ((uint2*)g_out1)[(size_t)node * 32 + lane] = st;
}

__device__ __forceinline__ void acc_h2(float2& a, __half2 h) {
    float2 f = __half22float2(h);
    a.x += f.x; a.y += f.y;
}

// ---------------- aggregation layer 2 (DIM=64, fp16 in, pool) ----------
__global__ __launch_bounds__(256) void k_agg2(const float* __restrict__ bias,
                                              const int* __restrict__ batch, int n) {
    const __half2* hs = (const __half2*)g_hs2;   // row = 32 half2
    int warp = (blockIdx.x * blockDim.x + threadIdx.x) >> 5;
    int lane = threadIdx.x & 31;
    if (warp >= n) return;
    int node = warp;

    float2 a0 = __half22float2(hs[(size_t)node * 32 + lane]);

    int e = g_rowptr[node];
    int t = g_rowptr[node + 1];
    for (; e + 4 <= t; e += 4) {
        int c0 = g_col[e], c1 = g_col[e + 1], c2 = g_col[e + 2], c3 = g_col[e + 3];
        __half2 v0 = hs[(size_t)c0 * 32 + lane];
        __half2 v1 = hs[(size_t)c1 * 32 + lane];
        __half2 v2 = hs[(size_t)c2 * 32 + lane];
        __half2 v3 = hs[(size_t)c3 * 32 + lane];
        acc_h2(a0, v0); acc_h2(a0, v1); acc_h2(a0, v2); acc_h2(a0, v3);
    }
    for (; e < t; e++)
        acc_h2(a0, hs[(size_t)g_col[e] * 32 + lane]);

    float dv = g_dinv[node];
    float2 bb = ((const float2*)bias)[lane];
    int gidx = batch[node];
    atomicAdd(&g_gsum[gidx * D_OUT + 2 * lane + 0], fmaf(a0.x, dv, bb.x));
    atomicAdd(&g_gsum[gidx * D_OUT + 2 * lane + 1], fmaf(a0.y, dv, bb.y));
}

// ---------------- final divide + re-zero pool state ----------------
__global__ void k_final(float* __restrict__ out) {
    int i = blockIdx.x * blockDim.x + threadIdx.x;
    if (i < NG * D_OUT) {
        int g = i / D_OUT;
        float c = (float)max(g_gcnt[g], 1);
        out[i] = g_gsum[i] / c;
        g_gsum[i] = 0.0f;
    }
    if (i < NG) g_gcnt[i] = 0;
}

// ---------------- launch (graph-capturable; no host API calls) ----------
extern "C" void kernel_launch(void* const* d_in, const int* in_sizes, int n_in,
                              void* d_out, int out_size) {
    const float* x = nullptr; const int* ei = nullptr; const int* batch = nullptr;
    const float* W1 = nullptr; const float* b1 = nullptr;
    const float* W2 = nullptr; const float* b2 = nullptr;
    for (int i = 0; i < n_in; i++) {
        switch (in_sizes[i]) {
            case NN * D_IN:      x     = (const float*)d_in[i]; break;
            case 2 * NE:         ei    = (const int*)d_in[i];   break;
            case NN:             batch = (const int*)d_in[i];   break;
            case D_IN * D_HID:   W1    = (const float*)d_in[i]; break;
            case D_HID * D_OUT:  W2    = (const float*)d_in[i]; break;
            case D_HID:          b1    = (const float*)d_in[i]; break;
            case D_OUT:          b2    = (const float*)d_in[i]; break;
        }
    }
    float* out = (float*)d_out;

    const int n = NN, e = NE;
    const int e4 = NE / 4;                // 150000 (NE % 4 == 0)
    const int nb256n = (n + 255) / 256;   // 196
    const int nb256e4 = (e4 + 255) / 256; // 586

    k_deg<<<nb256e4, 256>>>(ei, batch, W1, W2, e4, n);
    k_scan1<<<nb256n, 256>>>(n);
    k_scan3<<<nb256n, 256>>>(n, e, nb256n);
    k_fill<<<nb256e4, 256>>>(ei, e4, n);

    int gb = (n + 63) / 64;               // 782
    k_mma<128, 1><<<gb, 256>>>(x, n);
    k_agg1<<<(n + 7) / 8, 256>>>(b1, n);
    k_mma<64, 2><<<gb, 256>>>(nullptr, n);
    k_agg2<<<(n + 7) / 8, 256>>>(b2, batch, n);
    k_final<<<(NG * D_OUT + 255) / 256, 256>>>(out);
}